// round 14
// baseline (speedup 1.0000x reference)
#include <cuda_runtime.h>

// FINAL: out_i = sign(x) * u_i / ||u||, u = W[0,1:4]; 0 when x == 0.
// The reference's spectral norm, 10-step Euler scan, and normalization all
// cancel algebraically; only the sign of depth and the unit direction of
// W[0,1:4] survive. Steady state is bound by the mandatory 64MB of LTS
// traffic (16MB read + 48MB write) + replay overhead; this shape is the
// empirical optimum over 13 measured variants.

#define HWPIX (512 * 512)            // 2^18 elements per plane
#define NBATCH 16
#define F4_PER_THREAD 4
#define THREADS 128
#define BLOCK_ELEMS (THREADS * F4_PER_THREAD * 4)   // 2048 elems per block

__global__ __launch_bounds__(THREADS) void scene_normal_kernel(
    const float4* __restrict__ depth4,   // [16*512*512/4]
    const float*  __restrict__ Wm,       // [8,8] row-major
    float* __restrict__ out)             // [16,3,512,512] flat
{
    const float u1 = Wm[1];
    const float u2 = Wm[2];
    const float u3 = Wm[3];
    const float r  = rsqrtf(u1 * u1 + u2 * u2 + u3 * u3);
    const float c1 = u1 * r, c2 = u2 * r, c3 = u3 * r;

    // Block-contiguous chunk; single wave; all accesses warp-coalesced.
    const int n0   = blockIdx.x * BLOCK_ELEMS;
    const int b    = n0 >> 18;                 // BLOCK_ELEMS divides HWPIX
    const int rem0 = n0 & (HWPIX - 1);

    const float4* in4 = depth4 + (n0 >> 2) + threadIdx.x;
    float* basep = out + (size_t)b * 3 * HWPIX + rem0;
    float4* o1 = reinterpret_cast<float4*>(basep) + threadIdx.x;
    float4* o2 = reinterpret_cast<float4*>(basep + HWPIX) + threadIdx.x;
    float4* o3 = reinterpret_cast<float4*>(basep + 2 * HWPIX) + threadIdx.x;

    // Front-batch all loads (MLP = 4)
    float4 x[F4_PER_THREAD];
#pragma unroll
    for (int i = 0; i < F4_PER_THREAD; i++)
        x[i] = in4[i * THREADS];

#pragma unroll
    for (int i = 0; i < F4_PER_THREAD; i++) {
        const float s0 = (x[i].x > 0.f) ? 1.f : ((x[i].x < 0.f) ? -1.f : 0.f);
        const float s1 = (x[i].y > 0.f) ? 1.f : ((x[i].y < 0.f) ? -1.f : 0.f);
        const float s2 = (x[i].z > 0.f) ? 1.f : ((x[i].z < 0.f) ? -1.f : 0.f);
        const float s3 = (x[i].w > 0.f) ? 1.f : ((x[i].w < 0.f) ? -1.f : 0.f);

        float4 o;
        o.x = s0 * c1; o.y = s1 * c1; o.z = s2 * c1; o.w = s3 * c1;
        o1[i * THREADS] = o;
        o.x = s0 * c2; o.y = s1 * c2; o.z = s2 * c2; o.w = s3 * c2;
        o2[i * THREADS] = o;
        o.x = s0 * c3; o.y = s1 * c3; o.z = s2 * c3; o.w = s3 * c3;
        o3[i * THREADS] = o;
    }
}

extern "C" void kernel_launch(void* const* d_in, const int* in_sizes, int n_in,
                              void* d_out, int out_size)
{
    const float4* depth4 = (const float4*)d_in[0];
    const float*  Wm     = (const float*)d_in[1];
    float* out           = (float*)d_out;

    const int n_elems = NBATCH * HWPIX;          // 4,194,304
    const int blocks  = n_elems / BLOCK_ELEMS;   // 2048 (single wave, ~14 CTAs/SM)

    scene_normal_kernel<<<blocks, THREADS>>>(depth4, Wm, out);
}

// round 15
// speedup vs baseline: 1.0175x; 1.0175x over previous
#include <cuda_runtime.h>

// FINAL: out_i = sign(x) * u_i / ||u||, u = W[0,1:4]; 0 when x == 0.
// The reference's spectral norm, 10-step Euler scan, and normalization all
// cancel algebraically; only the sign of depth and the unit direction of
// W[0,1:4] survive. Steady state is bound by the mandatory 64MB of LTS
// traffic (16MB read + 48MB write) plus graph-replay overhead. This is the
// best-measured configuration over 14 rounds (12.352us sample):
// single wave, 1024 CTAs x 256 threads, block-contiguous 16KB chunks,
// front-batched float4 loads (MLP=4), plain STG.128 stores.

#define HWPIX (512 * 512)            // 2^18 elements per plane
#define NBATCH 16
#define F4_PER_THREAD 4
#define THREADS 256
#define BLOCK_ELEMS (THREADS * F4_PER_THREAD * 4)   // 4096 elems per block

__global__ __launch_bounds__(THREADS) void scene_normal_kernel(
    const float4* __restrict__ depth4,   // [16*512*512/4]
    const float*  __restrict__ Wm,       // [8,8] row-major
    float* __restrict__ out)             // [16,3,512,512] flat
{
    const float u1 = Wm[1];
    const float u2 = Wm[2];
    const float u3 = Wm[3];
    const float r  = rsqrtf(u1 * u1 + u2 * u2 + u3 * u3);
    const float c1 = u1 * r, c2 = u2 * r, c3 = u3 * r;

    // Block-contiguous chunk; one wave; all accesses warp-coalesced.
    const int n0   = blockIdx.x * BLOCK_ELEMS;        // first element of block
    const int b    = n0 >> 18;                        // HWPIX | BLOCK_ELEMS*64
    const int rem0 = n0 & (HWPIX - 1);

    const float4* in4 = depth4 + (n0 >> 2) + threadIdx.x;
    float* basep = out + (size_t)b * 3 * HWPIX + rem0;
    float4* o1 = reinterpret_cast<float4*>(basep) + threadIdx.x;
    float4* o2 = reinterpret_cast<float4*>(basep + HWPIX) + threadIdx.x;
    float4* o3 = reinterpret_cast<float4*>(basep + 2 * HWPIX) + threadIdx.x;

    // Front-batch all loads: MLP per thread = 4
    float4 x[F4_PER_THREAD];
#pragma unroll
    for (int i = 0; i < F4_PER_THREAD; i++)
        x[i] = in4[i * THREADS];

#pragma unroll
    for (int i = 0; i < F4_PER_THREAD; i++) {
        const float s0 = (x[i].x > 0.f) ? 1.f : ((x[i].x < 0.f) ? -1.f : 0.f);
        const float s1 = (x[i].y > 0.f) ? 1.f : ((x[i].y < 0.f) ? -1.f : 0.f);
        const float s2 = (x[i].z > 0.f) ? 1.f : ((x[i].z < 0.f) ? -1.f : 0.f);
        const float s3 = (x[i].w > 0.f) ? 1.f : ((x[i].w < 0.f) ? -1.f : 0.f);

        float4 o;
        o.x = s0 * c1; o.y = s1 * c1; o.z = s2 * c1; o.w = s3 * c1;
        o1[i * THREADS] = o;
        o.x = s0 * c2; o.y = s1 * c2; o.z = s2 * c2; o.w = s3 * c2;
        o2[i * THREADS] = o;
        o.x = s0 * c3; o.y = s1 * c3; o.z = s2 * c3; o.w = s3 * c3;
        o3[i * THREADS] = o;
    }
}

extern "C" void kernel_launch(void* const* d_in, const int* in_sizes, int n_in,
                              void* d_out, int out_size)
{
    const float4* depth4 = (const float4*)d_in[0];
    const float*  Wm     = (const float*)d_in[1];
    float* out           = (float*)d_out;

    const int n_elems = NBATCH * HWPIX;             // 4,194,304
    const int blocks  = n_elems / BLOCK_ELEMS;      // 1024 (single wave)

    scene_normal_kernel<<<blocks, THREADS>>>(depth4, Wm, out);
}

// round 16
// speedup vs baseline: 1.0201x; 1.0025x over previous
#include <cuda_runtime.h>

// FINAL: out_i = sign(x) * u_i / ||u||, u = W[0,1:4]; 0 when x == 0.
// The reference's spectral norm, 10-step Euler scan, and normalization all
// cancel algebraically; only the sign of depth and the unit direction of
// W[0,1:4] survive. Steady state is bound by the mandatory 64MB of LTS
// traffic (16MB read + 48MB write) plus graph-replay overhead; 15 measured
// variants (paths, widths, hints, MLP shapes, orderings, pipelines) are all
// within noise of this floor. Best-measured configuration:
// single wave, 1024 CTAs x 256 threads, block-contiguous 16KB chunks,
// front-batched float4 loads (MLP=4), plain STG.128 stores.

#define HWPIX (512 * 512)            // 2^18 elements per plane
#define NBATCH 16
#define F4_PER_THREAD 4
#define THREADS 256
#define BLOCK_ELEMS (THREADS * F4_PER_THREAD * 4)   // 4096 elems per block

__global__ __launch_bounds__(THREADS) void scene_normal_kernel(
    const float4* __restrict__ depth4,   // [16*512*512/4]
    const float*  __restrict__ Wm,       // [8,8] row-major
    float* __restrict__ out)             // [16,3,512,512] flat
{
    const float u1 = Wm[1];
    const float u2 = Wm[2];
    const float u3 = Wm[3];
    const float r  = rsqrtf(u1 * u1 + u2 * u2 + u3 * u3);
    const float c1 = u1 * r, c2 = u2 * r, c3 = u3 * r;

    // Block-contiguous chunk; one wave; all accesses warp-coalesced.
    const int n0   = blockIdx.x * BLOCK_ELEMS;        // first element of block
    const int b    = n0 >> 18;                        // HWPIX | BLOCK_ELEMS*64
    const int rem0 = n0 & (HWPIX - 1);

    const float4* in4 = depth4 + (n0 >> 2) + threadIdx.x;
    float* basep = out + (size_t)b * 3 * HWPIX + rem0;
    float4* o1 = reinterpret_cast<float4*>(basep) + threadIdx.x;
    float4* o2 = reinterpret_cast<float4*>(basep + HWPIX) + threadIdx.x;
    float4* o3 = reinterpret_cast<float4*>(basep + 2 * HWPIX) + threadIdx.x;

    // Front-batch all loads: MLP per thread = 4
    float4 x[F4_PER_THREAD];
#pragma unroll
    for (int i = 0; i < F4_PER_THREAD; i++)
        x[i] = in4[i * THREADS];

#pragma unroll
    for (int i = 0; i < F4_PER_THREAD; i++) {
        const float s0 = (x[i].x > 0.f) ? 1.f : ((x[i].x < 0.f) ? -1.f : 0.f);
        const float s1 = (x[i].y > 0.f) ? 1.f : ((x[i].y < 0.f) ? -1.f : 0.f);
        const float s2 = (x[i].z > 0.f) ? 1.f : ((x[i].z < 0.f) ? -1.f : 0.f);
        const float s3 = (x[i].w > 0.f) ? 1.f : ((x[i].w < 0.f) ? -1.f : 0.f);

        float4 o;
        o.x = s0 * c1; o.y = s1 * c1; o.z = s2 * c1; o.w = s3 * c1;
        o1[i * THREADS] = o;
        o.x = s0 * c2; o.y = s1 * c2; o.z = s2 * c2; o.w = s3 * c2;
        o2[i * THREADS] = o;
        o.x = s0 * c3; o.y = s1 * c3; o.z = s2 * c3; o.w = s3 * c3;
        o3[i * THREADS] = o;
    }
}

extern "C" void kernel_launch(void* const* d_in, const int* in_sizes, int n_in,
                              void* d_out, int out_size)
{
    const float4* depth4 = (const float4*)d_in[0];
    const float*  Wm     = (const float*)d_in[1];
    float* out           = (float*)d_out;

    const int n_elems = NBATCH * HWPIX;             // 4,194,304
    const int blocks  = n_elems / BLOCK_ELEMS;      // 1024 (single wave)

    scene_normal_kernel<<<blocks, THREADS>>>(depth4, Wm, out);
}